// round 9
// baseline (speedup 1.0000x reference)
#include <cuda_runtime.h>
#include <cuda_fp16.h>
#include <math.h>

#define Nn 100000
#define Ee 1600000
#define Hh 64
#define Ll 3
#define Kt 8192
#define CUT 5.0f
#define INVBN 0.9995003747f   // 1/sqrt(1+1e-3)
#define NB1 98                // ceil(Nn/1024) scan blocks

typedef unsigned long long ull;

// ---- static device scratch ----
__device__ __align__(256) float  g_h[Nn * Hh];      // node features, 25.6 MB
__device__ __align__(256) __half g_hh[Nn * Hh];     // fp16 gather mirror, 12.8 MB
__device__ __align__(256) float  g_agg[Nn * Hh];    // aggregation target, 25.6 MB
__device__ __align__(256) int4   g_ep4[Ee];         // (col, fs0, fs1, fs2), 25.6 MB
__device__ int   g_cnt[Nn];
__device__ int   g_off[Nn];
__device__ int   g_cur[Nn];
__device__ ull   g_state[NB1];                      // lookback scan states
__device__ float g_table[Ll * Kt];
__device__ float g_mean[Hh];

__device__ __forceinline__ float sp(float x) {      // softplus, stable
    return fmaxf(x, 0.0f) + log1pf(expf(-fabsf(x)));
}

// ---- table: fs(d)*cut(d); fW2 rowsums computed per-block in smem ----
__global__ void table_kernel(const float* __restrict__ fW1,
                             const float* __restrict__ fb1,
                             const float* __restrict__ fW2,
                             const float* __restrict__ fb2) {
    int t = blockIdx.x * 256 + threadIdx.x;       // grid 96x256 == Ll*Kt
    int l = t >> 13;                              // same l for whole block
    __shared__ float sw2[64];
    __shared__ float sb2;
    if (threadIdx.x < 64) {
        const float* p = fW2 + l * Hh * Hh + threadIdx.x * Hh;
        float s = 0.0f;
        #pragma unroll
        for (int k = 0; k < Hh; k++) s += p[k];
        sw2[threadIdx.x] = s;
    }
    if (threadIdx.x == 64) {
        float s = 0.0f;
        for (int k = 0; k < Hh; k++) s += fb2[l * Hh + k];
        sb2 = s;
    }
    __syncthreads();
    int k = t & (Kt - 1);
    float d = k * (CUT / (float)(Kt - 1));
    float s = d * (2.0f / CUT) - 1.0f;
    const float* w1 = fW1 + l * Hh;
    const float* b1 = fb1 + l * Hh;
    float acc = sb2;
    #pragma unroll 8
    for (int j = 0; j < Hh; j++)
        acc = fmaf(tanhf(fmaf(s, w1[j], b1[j])), sw2[j], acc);
    float cut = 0.5f * (cosf(d * (float)(M_PI / 5.0)) + 1.0f);
    g_table[t] = acc * cut;
}

// ---- embedding: h = x @ emb_W + emb_b ; fp16 mirror; zero cnt/mean/state ----
__global__ void embed_kernel(const float* __restrict__ x,
                             const float* __restrict__ W,
                             const float* __restrict__ b) {
    __shared__ float sW[16 * 64];
    __shared__ float sb[64];
    int tid = threadIdx.x;
    for (int i = tid; i < 16 * 64; i += 256) sW[i] = W[i];
    if (tid < 64) sb[tid] = b[tid];
    __syncthreads();
    int t = blockIdx.x * 256 + tid;
    // side duties (disjoint ranges, cheap)
    if (t < Nn) g_cnt[t] = 0;
    if (t < Hh) g_mean[t] = 0.0f;
    if (t < NB1) g_state[t] = 0ull;
    if (t >= Nn * 16) return;
    int n = t >> 4, q = t & 15, j0 = q * 4;
    const float* xr = x + n * 16;
    float4 acc = make_float4(sb[j0], sb[j0 + 1], sb[j0 + 2], sb[j0 + 3]);
    #pragma unroll
    for (int i = 0; i < 16; i++) {
        float xi = xr[i];
        acc.x = fmaf(xi, sW[i * 64 + j0 + 0], acc.x);
        acc.y = fmaf(xi, sW[i * 64 + j0 + 1], acc.y);
        acc.z = fmaf(xi, sW[i * 64 + j0 + 2], acc.z);
        acc.w = fmaf(xi, sW[i * 64 + j0 + 3], acc.w);
    }
    ((float4*)g_h)[t] = acc;
    __half2* hh = (__half2*)(g_hh + n * 64 + j0);
    hh[0] = __floats2half2_rn(acc.x, acc.y);
    hh[1] = __floats2half2_rn(acc.z, acc.w);
}

__global__ void hist_kernel(const int* __restrict__ eidx) {
    int e = blockIdx.x * blockDim.x + threadIdx.x;
    if (e < Ee) atomicAdd(&g_cnt[eidx[e]], 1);
}

// ---- single-pass decoupled-lookback exclusive scan of g_cnt -> g_off/g_cur ----
__global__ void __launch_bounds__(1024) scan_kernel() {
    int bid = blockIdx.x;
    int i = bid * 1024 + threadIdx.x;
    int v = (i < Nn) ? g_cnt[i] : 0;
    int lane = threadIdx.x & 31, w = threadIdx.x >> 5;
    int x = v;
    #pragma unroll
    for (int off = 1; off < 32; off <<= 1) {
        int y = __shfl_up_sync(0xffffffff, x, off);
        if (lane >= off) x += y;
    }
    __shared__ int wsum[32], wpre[32];
    __shared__ int stotal, sprefix;
    if (lane == 31) wsum[w] = x;
    __syncthreads();
    if (threadIdx.x < 32) {
        int s = wsum[threadIdx.x];
        int xs = s;
        #pragma unroll
        for (int off = 1; off < 32; off <<= 1) {
            int y = __shfl_up_sync(0xffffffff, xs, off);
            if ((int)threadIdx.x >= off) xs += y;
        }
        wpre[threadIdx.x] = xs - s;
        if (threadIdx.x == 31) stotal = xs;
    }
    __syncthreads();
    int total = stotal;
    if (threadIdx.x == 0) {
        if (bid == 0) {
            sprefix = 0;
            atomicExch(&g_state[0], (2ull << 32) | (unsigned)total);
        } else {
            atomicExch(&g_state[bid], (1ull << 32) | (unsigned)total);
            ull run = 0;
            int p = bid - 1;
            while (true) {
                ull sv = atomicAdd(&g_state[p], 0ull);
                unsigned st = (unsigned)(sv >> 32);
                if (st == 0u) { __nanosleep(32); continue; }
                run += (unsigned)sv;
                if (st == 2u) break;
                p--;
            }
            sprefix = (int)run;
            atomicExch(&g_state[bid], (2ull << 32) | (unsigned)(run + total));
        }
    }
    __syncthreads();
    if (i < Nn) {
        int o = x - v + wpre[w] + sprefix;
        g_off[i] = o;
        g_cur[i] = o;
    }
}

// scatter edges into CSR order; one int4 record (col, fs0, fs1, fs2)
__global__ void fill_kernel(const int* __restrict__ eidx,
                            const float* __restrict__ dist) {
    int e = blockIdx.x * blockDim.x + threadIdx.x;
    if (e >= Ee) return;
    int r = eidx[e];
    int c = eidx[Ee + e];
    float d = __ldg(dist + e);
    float u = d * ((float)(Kt - 1) / CUT);
    u = fminf(fmaxf(u, 0.0f), (float)(Kt - 2) + 0.999f);
    int i = (int)u;
    float fr = u - (float)i;
    float fs[Ll];
    #pragma unroll
    for (int l = 0; l < Ll; l++) {
        const float* tb = g_table + l * Kt;
        float t0 = __ldg(tb + i), t1 = __ldg(tb + i + 1);
        fs[l] = fmaf(fr, t1 - t0, t0);
    }
    int pos = atomicAdd(&g_cur[r], 1);
    g_ep4[pos] = make_int4(c, __float_as_int(fs[0]),
                           __float_as_int(fs[1]), __float_as_int(fs[2]));
}

// ============ per-layer edge aggregation: warp per row, whole-warp per edge ====
// Records loaded coalesced (1/lane), broadcast via shfl; each lane gathers one
// half2 (LDG.32) per edge -> 128B/edge; accumulate fp32.
__global__ void __launch_bounds__(256) agg_kernel(int l) {
    int gw = (blockIdx.x * 256 + threadIdx.x) >> 5;
    if (gw >= Nn) return;
    int lane = threadIdx.x & 31;
    int beg = g_off[gw], deg = g_cnt[gw];
    float2 acc = make_float2(0.0f, 0.0f);
    const __half2* hb = (const __half2*)g_hh;
    for (int base = 0; base < deg; base += 32) {
        int rem = deg - base;
        if (rem > 32) rem = 32;
        int col_r = 0, fs_r = 0;
        if (lane < rem) {
            int4 m = __ldg(&g_ep4[beg + base + lane]);
            col_r = m.x;
            fs_r = (l == 0) ? m.y : (l == 1 ? m.z : m.w);
        }
        int d = 0;
        #pragma unroll 4
        for (; d + 4 <= rem; d += 4) {
            int c0 = __shfl_sync(0xffffffff, col_r, d + 0);
            int c1 = __shfl_sync(0xffffffff, col_r, d + 1);
            int c2 = __shfl_sync(0xffffffff, col_r, d + 2);
            int c3 = __shfl_sync(0xffffffff, col_r, d + 3);
            float f0 = __int_as_float(__shfl_sync(0xffffffff, fs_r, d + 0));
            float f1 = __int_as_float(__shfl_sync(0xffffffff, fs_r, d + 1));
            float f2 = __int_as_float(__shfl_sync(0xffffffff, fs_r, d + 2));
            float f3 = __int_as_float(__shfl_sync(0xffffffff, fs_r, d + 3));
            __half2 r0 = __ldg(hb + c0 * 32 + lane);
            __half2 r1 = __ldg(hb + c1 * 32 + lane);
            __half2 r2 = __ldg(hb + c2 * 32 + lane);
            __half2 r3 = __ldg(hb + c3 * 32 + lane);
            float2 v0 = __half22float2(r0);
            float2 v1 = __half22float2(r1);
            float2 v2 = __half22float2(r2);
            float2 v3 = __half22float2(r3);
            acc.x = fmaf(v0.x, f0, acc.x);
            acc.y = fmaf(v0.y, f0, acc.y);
            acc.x = fmaf(v1.x, f1, acc.x);
            acc.y = fmaf(v1.y, f1, acc.y);
            acc.x = fmaf(v2.x, f2, acc.x);
            acc.y = fmaf(v2.y, f2, acc.y);
            acc.x = fmaf(v3.x, f3, acc.x);
            acc.y = fmaf(v3.y, f3, acc.y);
        }
        for (; d < rem; d++) {
            int c0 = __shfl_sync(0xffffffff, col_r, d);
            float f0 = __int_as_float(__shfl_sync(0xffffffff, fs_r, d));
            float2 v0 = __half22float2(__ldg(hb + c0 * 32 + lane));
            acc.x = fmaf(v0.x, f0, acc.x);
            acc.y = fmaf(v0.y, f0, acc.y);
        }
    }
    ((float2*)g_agg)[gw * 32 + lane] = acc;
}

// ============ node MLP: register weights, thread-per-column, 4 nodes/iter ======
__global__ void __launch_bounds__(128, 3) node_kernel(
    const float* __restrict__ iW1, const float* __restrict__ ib1,
    const float* __restrict__ iW2, const float* __restrict__ ib2,
    const float* __restrict__ gam, const float* __restrict__ bet,
    int flags) {   // bit0: accumulate mean; bit1: write fp16 mirror
    __shared__ __align__(16) float sa[4][64];
    __shared__ __align__(16) float st[4][64];
    __shared__ float sm[128];
    int tid = threadIdx.x;
    int half = tid >> 6, j = tid & 63;
    float w1[64], w2[64];
    #pragma unroll
    for (int i = 0; i < 64; i++) {
        w1[i] = iW1[i * 64 + j];
        w2[i] = iW2[i * 64 + j];
    }
    float b1 = ib1[j], b2 = ib2[j];
    float gm = gam[j] * INVBN, bt = bet[j];
    float ms = 0.0f;
    int do_mean = flags & 1, do_half = flags & 2;

    for (int n0 = blockIdx.x * 4; n0 < Nn; n0 += gridDim.x * 4) {
        int nA = n0 + half, nB = n0 + 2 + half;      // Nn % 4 == 0 -> valid
        float aA = g_agg[nA * 64 + j];
        float aB = g_agg[nB * 64 + j];
        sa[half][j] = aA;
        sa[half + 2][j] = aB;
        __syncthreads();
        float acc0 = b1, acc1 = b1;
        const float4* A0 = (const float4*)sa[half];
        const float4* A1 = (const float4*)sa[half + 2];
        #pragma unroll
        for (int i4 = 0; i4 < 16; i4++) {
            float4 u = A0[i4];
            float4 v = A1[i4];
            acc0 = fmaf(u.x, w1[i4 * 4 + 0], acc0);
            acc1 = fmaf(v.x, w1[i4 * 4 + 0], acc1);
            acc0 = fmaf(u.y, w1[i4 * 4 + 1], acc0);
            acc1 = fmaf(v.y, w1[i4 * 4 + 1], acc1);
            acc0 = fmaf(u.z, w1[i4 * 4 + 2], acc0);
            acc1 = fmaf(v.z, w1[i4 * 4 + 2], acc1);
            acc0 = fmaf(u.w, w1[i4 * 4 + 3], acc0);
            acc1 = fmaf(v.w, w1[i4 * 4 + 3], acc1);
        }
        st[half][j] = sp(acc0);
        st[half + 2][j] = sp(acc1);
        __syncthreads();
        float o0 = b2, o1 = b2;
        const float4* T0 = (const float4*)st[half];
        const float4* T1 = (const float4*)st[half + 2];
        #pragma unroll
        for (int i4 = 0; i4 < 16; i4++) {
            float4 u = T0[i4];
            float4 v = T1[i4];
            o0 = fmaf(u.x, w2[i4 * 4 + 0], o0);
            o1 = fmaf(v.x, w2[i4 * 4 + 0], o1);
            o0 = fmaf(u.y, w2[i4 * 4 + 1], o0);
            o1 = fmaf(v.y, w2[i4 * 4 + 1], o1);
            o0 = fmaf(u.z, w2[i4 * 4 + 2], o0);
            o1 = fmaf(v.z, w2[i4 * 4 + 2], o1);
            o0 = fmaf(u.w, w2[i4 * 4 + 3], o0);
            o1 = fmaf(v.w, w2[i4 * 4 + 3], o1);
        }
        float h0 = g_h[nA * 64 + j] + fmaf(o0, gm, bt);
        float h1 = g_h[nB * 64 + j] + fmaf(o1, gm, bt);
        g_h[nA * 64 + j] = h0;
        g_h[nB * 64 + j] = h1;
        if (do_half) {
            g_hh[nA * 64 + j] = __float2half_rn(h0);
            g_hh[nB * 64 + j] = __float2half_rn(h1);
        }
        ms += h0 + h1;
    }
    if (do_mean) {
        sm[tid] = ms;
        __syncthreads();
        if (half == 0) atomicAdd(&g_mean[j], sm[j] + sm[j + 64]);
    }
}

// ---- final head ----
__global__ void final_kernel(const float* __restrict__ oW1, const float* __restrict__ ob1,
                             const float* __restrict__ og1, const float* __restrict__ obt1,
                             const float* __restrict__ oW2, const float* __restrict__ ob2,
                             const float* __restrict__ og2, const float* __restrict__ obt2,
                             const float* __restrict__ fiW, const float* __restrict__ fib,
                             float* __restrict__ out) {
    __shared__ float gv[64], s1[32], s2[32];
    int t = threadIdx.x;  // 64 threads
    gv[t] = g_mean[t] * (1.0f / (float)Nn);
    __syncthreads();
    if (t < 32) {
        float acc = ob1[t];
        #pragma unroll
        for (int i = 0; i < 64; i++) acc = fmaf(gv[i], oW1[i * 32 + t], acc);
        s1[t] = fmaf(sp(acc) * INVBN, og1[t], obt1[t]);
    }
    __syncthreads();
    if (t < 32) {
        float acc = ob2[t];
        #pragma unroll
        for (int i = 0; i < 32; i++) acc = fmaf(s1[i], oW2[i * 32 + t], acc);
        s2[t] = fmaf(sp(acc) * INVBN, og2[t], obt2[t]);
    }
    __syncthreads();
    if (t < 3) {
        float acc = fib[t];
        #pragma unroll
        for (int i = 0; i < 32; i++) acc = fmaf(s2[i], fiW[i * 3 + t], acc);
        out[t] = acc;
    }
}

extern "C" void kernel_launch(void* const* d_in, const int* in_sizes, int n_in,
                              void* d_out, int out_size) {
    const float* x    = (const float*)d_in[0];
    const int*   eidx = (const int*)  d_in[1];
    const float* dist = (const float*)d_in[2];
    const float* embW = (const float*)d_in[4];
    const float* embB = (const float*)d_in[5];
    const float* fW1  = (const float*)d_in[6];
    const float* fb1  = (const float*)d_in[7];
    const float* fW2  = (const float*)d_in[8];
    const float* fb2  = (const float*)d_in[9];
    const float* iW1  = (const float*)d_in[10];
    const float* ib1  = (const float*)d_in[11];
    const float* iW2  = (const float*)d_in[12];
    const float* ib2  = (const float*)d_in[13];
    const float* gam  = (const float*)d_in[14];
    const float* bet  = (const float*)d_in[15];
    const float* oW1  = (const float*)d_in[16];
    const float* ob1  = (const float*)d_in[17];
    const float* og1  = (const float*)d_in[18];
    const float* obt1 = (const float*)d_in[19];
    const float* oW2  = (const float*)d_in[20];
    const float* ob2  = (const float*)d_in[21];
    const float* og2  = (const float*)d_in[22];
    const float* obt2 = (const float*)d_in[23];
    const float* fiW  = (const float*)d_in[24];
    const float* fib  = (const float*)d_in[25];
    float* out = (float*)d_out;

    table_kernel<<<(Ll * Kt) / 256, 256>>>(fW1, fb1, fW2, fb2);
    embed_kernel<<<(Nn * 16 + 255) / 256, 256>>>(x, embW, embB);
    hist_kernel<<<(Ee + 255) / 256, 256>>>(eidx);
    scan_kernel<<<NB1, 1024>>>();
    fill_kernel<<<(Ee + 255) / 256, 256>>>(eidx, dist);

    for (int l = 0; l < Ll; l++) {
        agg_kernel<<<(Nn * 32 + 255) / 256, 256>>>(l);
        int flags = (l == Ll - 1) ? 1 : 2;   // last layer: mean, no mirror
        node_kernel<<<444, 128>>>(iW1 + l * 4096, ib1 + l * 64,
                                  iW2 + l * 4096, ib2 + l * 64,
                                  gam + l * 64, bet + l * 64, flags);
    }

    final_kernel<<<1, 64>>>(oW1, ob1, og1, obt1, oW2, ob2, og2, obt2,
                            fiW, fib, out);
}

// round 10
// speedup vs baseline: 1.2401x; 1.2401x over previous
#include <cuda_runtime.h>
#include <math.h>

#define Nn 100000
#define Ee 1600000
#define Hh 64
#define Ll 3
#define Kt 8192
#define CUT 5.0f
#define INVBN 0.9995003747f   // 1/sqrt(1+1e-3)
#define NB1 98                // ceil(Nn/1024) scan blocks

typedef unsigned long long ull;

// ---- static device scratch ----
__device__ __align__(256) float g_h[Nn * Hh];       // node features, 25.6 MB
__device__ __align__(256) float g_agg[Nn * Hh];     // aggregation target, 25.6 MB
__device__ __align__(256) int4  g_ep4[Ee];          // (col, fs0, fs1, fs2), 25.6 MB
__device__ int   g_cnt[Nn];
__device__ int   g_off[Nn];
__device__ int   g_cur[Nn];
__device__ ull   g_state[NB1];                      // lookback scan states
__device__ float g_table[Ll * Kt];
__device__ float g_mean[Hh];

__device__ __forceinline__ float sp(float x) {      // softplus, stable
    return fmaxf(x, 0.0f) + log1pf(expf(-fabsf(x)));
}

// ---- table: fs(d)*cut(d); fW2 rowsums computed per-block in smem ----
__global__ void table_kernel(const float* __restrict__ fW1,
                             const float* __restrict__ fb1,
                             const float* __restrict__ fW2,
                             const float* __restrict__ fb2) {
    int t = blockIdx.x * 256 + threadIdx.x;       // grid 96x256 == Ll*Kt
    int l = t >> 13;                              // same l for whole block
    __shared__ float sw2[64];
    __shared__ float sb2;
    if (threadIdx.x < 64) {
        const float* p = fW2 + l * Hh * Hh + threadIdx.x * Hh;
        float s = 0.0f;
        #pragma unroll
        for (int k = 0; k < Hh; k++) s += p[k];
        sw2[threadIdx.x] = s;
    }
    if (threadIdx.x == 64) {
        float s = 0.0f;
        for (int k = 0; k < Hh; k++) s += fb2[l * Hh + k];
        sb2 = s;
    }
    __syncthreads();
    int k = t & (Kt - 1);
    float d = k * (CUT / (float)(Kt - 1));
    float s = d * (2.0f / CUT) - 1.0f;
    const float* w1 = fW1 + l * Hh;
    const float* b1 = fb1 + l * Hh;
    float acc = sb2;
    #pragma unroll 8
    for (int j = 0; j < Hh; j++)
        acc = fmaf(tanhf(fmaf(s, w1[j], b1[j])), sw2[j], acc);
    float cut = 0.5f * (cosf(d * (float)(M_PI / 5.0)) + 1.0f);
    g_table[t] = acc * cut;
}

// ---- embedding: h = x @ emb_W + emb_b ; also zero cnt/mean/scan-state ----
__global__ void embed_kernel(const float* __restrict__ x,
                             const float* __restrict__ W,
                             const float* __restrict__ b) {
    __shared__ float sW[16 * 64];
    __shared__ float sb[64];
    int tid = threadIdx.x;
    for (int i = tid; i < 16 * 64; i += 256) sW[i] = W[i];
    if (tid < 64) sb[tid] = b[tid];
    __syncthreads();
    int t = blockIdx.x * 256 + tid;
    // side duties (disjoint ranges, cheap)
    if (t < Nn) g_cnt[t] = 0;
    if (t < Hh) g_mean[t] = 0.0f;
    if (t < NB1) g_state[t] = 0ull;
    if (t >= Nn * 16) return;
    int n = t >> 4, q = t & 15, j0 = q * 4;
    const float* xr = x + n * 16;
    float4 acc = make_float4(sb[j0], sb[j0 + 1], sb[j0 + 2], sb[j0 + 3]);
    #pragma unroll
    for (int i = 0; i < 16; i++) {
        float xi = xr[i];
        acc.x = fmaf(xi, sW[i * 64 + j0 + 0], acc.x);
        acc.y = fmaf(xi, sW[i * 64 + j0 + 1], acc.y);
        acc.z = fmaf(xi, sW[i * 64 + j0 + 2], acc.z);
        acc.w = fmaf(xi, sW[i * 64 + j0 + 3], acc.w);
    }
    ((float4*)g_h)[t] = acc;
}

__global__ void hist_kernel(const int* __restrict__ eidx) {
    int e = blockIdx.x * blockDim.x + threadIdx.x;
    if (e < Ee) atomicAdd(&g_cnt[eidx[e]], 1);
}

// ---- single-pass decoupled-lookback exclusive scan of g_cnt -> g_off/g_cur ----
__global__ void __launch_bounds__(1024) scan_kernel() {
    int bid = blockIdx.x;
    int i = bid * 1024 + threadIdx.x;
    int v = (i < Nn) ? g_cnt[i] : 0;
    int lane = threadIdx.x & 31, w = threadIdx.x >> 5;
    int x = v;
    #pragma unroll
    for (int off = 1; off < 32; off <<= 1) {
        int y = __shfl_up_sync(0xffffffff, x, off);
        if (lane >= off) x += y;
    }
    __shared__ int wsum[32], wpre[32];
    __shared__ int stotal, sprefix;
    if (lane == 31) wsum[w] = x;
    __syncthreads();
    if (threadIdx.x < 32) {
        int s = wsum[threadIdx.x];
        int xs = s;
        #pragma unroll
        for (int off = 1; off < 32; off <<= 1) {
            int y = __shfl_up_sync(0xffffffff, xs, off);
            if ((int)threadIdx.x >= off) xs += y;
        }
        wpre[threadIdx.x] = xs - s;
        if (threadIdx.x == 31) stotal = xs;
    }
    __syncthreads();
    int total = stotal;
    if (threadIdx.x == 0) {
        if (bid == 0) {
            sprefix = 0;
            atomicExch(&g_state[0], (2ull << 32) | (unsigned)total);
        } else {
            atomicExch(&g_state[bid], (1ull << 32) | (unsigned)total);
            ull run = 0;
            int p = bid - 1;
            while (true) {
                ull sv = atomicAdd(&g_state[p], 0ull);
                unsigned st = (unsigned)(sv >> 32);
                if (st == 0u) { __nanosleep(32); continue; }
                run += (unsigned)sv;
                if (st == 2u) break;
                p--;
            }
            sprefix = (int)run;
            atomicExch(&g_state[bid], (2ull << 32) | (unsigned)(run + total));
        }
    }
    __syncthreads();
    if (i < Nn) {
        int o = x - v + wpre[w] + sprefix;
        g_off[i] = o;
        g_cur[i] = o;
    }
}

// scatter edges into CSR order; one int4 record (col, fs0, fs1, fs2)
__global__ void fill_kernel(const int* __restrict__ eidx,
                            const float* __restrict__ dist) {
    int e = blockIdx.x * blockDim.x + threadIdx.x;
    if (e >= Ee) return;
    int r = eidx[e];
    int c = eidx[Ee + e];
    float d = __ldg(dist + e);
    float u = d * ((float)(Kt - 1) / CUT);
    u = fminf(fmaxf(u, 0.0f), (float)(Kt - 2) + 0.999f);
    int i = (int)u;
    float fr = u - (float)i;
    float fs[Ll];
    #pragma unroll
    for (int l = 0; l < Ll; l++) {
        const float* tb = g_table + l * Kt;
        float t0 = __ldg(tb + i), t1 = __ldg(tb + i + 1);
        fs[l] = fmaf(fr, t1 - t0, t0);
    }
    int pos = atomicAdd(&g_cur[r], 1);
    g_ep4[pos] = make_int4(c, __float_as_int(fs[0]),
                           __float_as_int(fs[1]), __float_as_int(fs[2]));
}

// ============ per-layer edge aggregation: warp per row, whole-warp per edge ====
// (R8 proven form -- DO NOT TOUCH the inner loop)
__global__ void __launch_bounds__(256) agg_kernel(int l) {
    int gw = (blockIdx.x * 256 + threadIdx.x) >> 5;
    if (gw >= Nn) return;
    int lane = threadIdx.x & 31;
    int beg = g_off[gw], deg = g_cnt[gw];
    float2 acc = make_float2(0.0f, 0.0f);
    const float2* hb = (const float2*)g_h;
    for (int base = 0; base < deg; base += 32) {
        int rem = deg - base;
        if (rem > 32) rem = 32;
        int col_r = 0, fs_r = 0;
        if (lane < rem) {
            int4 m = __ldg(&g_ep4[beg + base + lane]);
            col_r = m.x;
            fs_r = (l == 0) ? m.y : (l == 1 ? m.z : m.w);
        }
        int d = 0;
        #pragma unroll 4
        for (; d + 4 <= rem; d += 4) {
            int c0 = __shfl_sync(0xffffffff, col_r, d + 0);
            int c1 = __shfl_sync(0xffffffff, col_r, d + 1);
            int c2 = __shfl_sync(0xffffffff, col_r, d + 2);
            int c3 = __shfl_sync(0xffffffff, col_r, d + 3);
            float f0 = __int_as_float(__shfl_sync(0xffffffff, fs_r, d + 0));
            float f1 = __int_as_float(__shfl_sync(0xffffffff, fs_r, d + 1));
            float f2 = __int_as_float(__shfl_sync(0xffffffff, fs_r, d + 2));
            float f3 = __int_as_float(__shfl_sync(0xffffffff, fs_r, d + 3));
            float2 v0 = __ldg(hb + c0 * 32 + lane);
            float2 v1 = __ldg(hb + c1 * 32 + lane);
            float2 v2 = __ldg(hb + c2 * 32 + lane);
            float2 v3 = __ldg(hb + c3 * 32 + lane);
            acc.x = fmaf(v0.x, f0, acc.x);
            acc.y = fmaf(v0.y, f0, acc.y);
            acc.x = fmaf(v1.x, f1, acc.x);
            acc.y = fmaf(v1.y, f1, acc.y);
            acc.x = fmaf(v2.x, f2, acc.x);
            acc.y = fmaf(v2.y, f2, acc.y);
            acc.x = fmaf(v3.x, f3, acc.x);
            acc.y = fmaf(v3.y, f3, acc.y);
        }
        for (; d < rem; d++) {
            int c0 = __shfl_sync(0xffffffff, col_r, d);
            float f0 = __int_as_float(__shfl_sync(0xffffffff, fs_r, d));
            float2 v0 = __ldg(hb + c0 * 32 + lane);
            acc.x = fmaf(v0.x, f0, acc.x);
            acc.y = fmaf(v0.y, f0, acc.y);
        }
    }
    ((float2*)g_agg)[gw * 32 + lane] = acc;
}

// ============ node MLP: register weights, thread-per-column, 8 nodes/iter ======
__global__ void __launch_bounds__(128, 3) node_kernel(
    const float* __restrict__ iW1, const float* __restrict__ ib1,
    const float* __restrict__ iW2, const float* __restrict__ ib2,
    const float* __restrict__ gam, const float* __restrict__ bet,
    int do_mean) {
    __shared__ __align__(16) float sa[8][64];
    __shared__ __align__(16) float st[8][64];
    __shared__ float sm[128];
    int tid = threadIdx.x;
    int half = tid >> 6, j = tid & 63;
    float w1[64], w2[64];
    #pragma unroll
    for (int i = 0; i < 64; i++) {
        w1[i] = iW1[i * 64 + j];
        w2[i] = iW2[i * 64 + j];
    }
    float b1 = ib1[j], b2 = ib2[j];
    float gm = gam[j] * INVBN, bt = bet[j];
    float ms = 0.0f;

    // Nn = 100000 = 8 * 12500 -> every group of 8 fully valid
    for (int n0 = blockIdx.x * 8; n0 < Nn; n0 += gridDim.x * 8) {
        #pragma unroll
        for (int q = 0; q < 4; q++)
            sa[half + 2 * q][j] = g_agg[(n0 + 2 * q + half) * 64 + j];
        __syncthreads();
        float a0 = b1, a1 = b1, a2 = b1, a3 = b1;
        const float4* A0 = (const float4*)sa[half + 0];
        const float4* A1 = (const float4*)sa[half + 2];
        const float4* A2 = (const float4*)sa[half + 4];
        const float4* A3 = (const float4*)sa[half + 6];
        #pragma unroll
        for (int i4 = 0; i4 < 16; i4++) {
            float4 u0 = A0[i4], u1 = A1[i4], u2 = A2[i4], u3 = A3[i4];
            float wa = w1[i4 * 4 + 0], wb = w1[i4 * 4 + 1];
            float wc = w1[i4 * 4 + 2], wd = w1[i4 * 4 + 3];
            a0 = fmaf(u0.x, wa, a0); a1 = fmaf(u1.x, wa, a1);
            a2 = fmaf(u2.x, wa, a2); a3 = fmaf(u3.x, wa, a3);
            a0 = fmaf(u0.y, wb, a0); a1 = fmaf(u1.y, wb, a1);
            a2 = fmaf(u2.y, wb, a2); a3 = fmaf(u3.y, wb, a3);
            a0 = fmaf(u0.z, wc, a0); a1 = fmaf(u1.z, wc, a1);
            a2 = fmaf(u2.z, wc, a2); a3 = fmaf(u3.z, wc, a3);
            a0 = fmaf(u0.w, wd, a0); a1 = fmaf(u1.w, wd, a1);
            a2 = fmaf(u2.w, wd, a2); a3 = fmaf(u3.w, wd, a3);
        }
        st[half + 0][j] = sp(a0);
        st[half + 2][j] = sp(a1);
        st[half + 4][j] = sp(a2);
        st[half + 6][j] = sp(a3);
        __syncthreads();
        float o0 = b2, o1 = b2, o2 = b2, o3 = b2;
        const float4* T0 = (const float4*)st[half + 0];
        const float4* T1 = (const float4*)st[half + 2];
        const float4* T2 = (const float4*)st[half + 4];
        const float4* T3 = (const float4*)st[half + 6];
        #pragma unroll
        for (int i4 = 0; i4 < 16; i4++) {
            float4 u0 = T0[i4], u1 = T1[i4], u2 = T2[i4], u3 = T3[i4];
            float wa = w2[i4 * 4 + 0], wb = w2[i4 * 4 + 1];
            float wc = w2[i4 * 4 + 2], wd = w2[i4 * 4 + 3];
            o0 = fmaf(u0.x, wa, o0); o1 = fmaf(u1.x, wa, o1);
            o2 = fmaf(u2.x, wa, o2); o3 = fmaf(u3.x, wa, o3);
            o0 = fmaf(u0.y, wb, o0); o1 = fmaf(u1.y, wb, o1);
            o2 = fmaf(u2.y, wb, o2); o3 = fmaf(u3.y, wb, o3);
            o0 = fmaf(u0.z, wc, o0); o1 = fmaf(u1.z, wc, o1);
            o2 = fmaf(u2.z, wc, o2); o3 = fmaf(u3.z, wc, o3);
            o0 = fmaf(u0.w, wd, o0); o1 = fmaf(u1.w, wd, o1);
            o2 = fmaf(u2.w, wd, o2); o3 = fmaf(u3.w, wd, o3);
        }
        #pragma unroll
        for (int q = 0; q < 4; q++) {
            float oq = (q == 0) ? o0 : (q == 1) ? o1 : (q == 2) ? o2 : o3;
            int n = n0 + 2 * q + half;
            float hn = g_h[n * 64 + j] + fmaf(oq, gm, bt);
            g_h[n * 64 + j] = hn;
            ms += hn;
        }
    }
    if (do_mean) {
        sm[tid] = ms;
        __syncthreads();
        if (half == 0) atomicAdd(&g_mean[j], sm[j] + sm[j + 64]);
    }
}

// ---- final head ----
__global__ void final_kernel(const float* __restrict__ oW1, const float* __restrict__ ob1,
                             const float* __restrict__ og1, const float* __restrict__ obt1,
                             const float* __restrict__ oW2, const float* __restrict__ ob2,
                             const float* __restrict__ og2, const float* __restrict__ obt2,
                             const float* __restrict__ fiW, const float* __restrict__ fib,
                             float* __restrict__ out) {
    __shared__ float gv[64], s1[32], s2[32];
    int t = threadIdx.x;  // 64 threads
    gv[t] = g_mean[t] * (1.0f / (float)Nn);
    __syncthreads();
    if (t < 32) {
        float acc = ob1[t];
        #pragma unroll
        for (int i = 0; i < 64; i++) acc = fmaf(gv[i], oW1[i * 32 + t], acc);
        s1[t] = fmaf(sp(acc) * INVBN, og1[t], obt1[t]);
    }
    __syncthreads();
    if (t < 32) {
        float acc = ob2[t];
        #pragma unroll
        for (int i = 0; i < 32; i++) acc = fmaf(s1[i], oW2[i * 32 + t], acc);
        s2[t] = fmaf(sp(acc) * INVBN, og2[t], obt2[t]);
    }
    __syncthreads();
    if (t < 3) {
        float acc = fib[t];
        #pragma unroll
        for (int i = 0; i < 32; i++) acc = fmaf(s2[i], fiW[i * 3 + t], acc);
        out[t] = acc;
    }
}

extern "C" void kernel_launch(void* const* d_in, const int* in_sizes, int n_in,
                              void* d_out, int out_size) {
    const float* x    = (const float*)d_in[0];
    const int*   eidx = (const int*)  d_in[1];
    const float* dist = (const float*)d_in[2];
    const float* embW = (const float*)d_in[4];
    const float* embB = (const float*)d_in[5];
    const float* fW1  = (const float*)d_in[6];
    const float* fb1  = (const float*)d_in[7];
    const float* fW2  = (const float*)d_in[8];
    const float* fb2  = (const float*)d_in[9];
    const float* iW1  = (const float*)d_in[10];
    const float* ib1  = (const float*)d_in[11];
    const float* iW2  = (const float*)d_in[12];
    const float* ib2  = (const float*)d_in[13];
    const float* gam  = (const float*)d_in[14];
    const float* bet  = (const float*)d_in[15];
    const float* oW1  = (const float*)d_in[16];
    const float* ob1  = (const float*)d_in[17];
    const float* og1  = (const float*)d_in[18];
    const float* obt1 = (const float*)d_in[19];
    const float* oW2  = (const float*)d_in[20];
    const float* ob2  = (const float*)d_in[21];
    const float* og2  = (const float*)d_in[22];
    const float* obt2 = (const float*)d_in[23];
    const float* fiW  = (const float*)d_in[24];
    const float* fib  = (const float*)d_in[25];
    float* out = (float*)d_out;

    table_kernel<<<(Ll * Kt) / 256, 256>>>(fW1, fb1, fW2, fb2);
    embed_kernel<<<(Nn * 16 + 255) / 256, 256>>>(x, embW, embB);
    hist_kernel<<<(Ee + 255) / 256, 256>>>(eidx);
    scan_kernel<<<NB1, 1024>>>();
    fill_kernel<<<(Ee + 255) / 256, 256>>>(eidx, dist);

    for (int l = 0; l < Ll; l++) {
        agg_kernel<<<(Nn * 32 + 255) / 256, 256>>>(l);
        node_kernel<<<444, 128>>>(iW1 + l * 4096, ib1 + l * 64,
                                  iW2 + l * 4096, ib2 + l * 64,
                                  gam + l * 64, bet + l * 64,
                                  (l == Ll - 1) ? 1 : 0);
    }

    final_kernel<<<1, 64>>>(oW1, ob1, og1, obt1, oW2, ob2, og2, obt2,
                            fiW, fib, out);
}